// round 2
// baseline (speedup 1.0000x reference)
#include <cuda_runtime.h>

#define PI_D 3.14159265358979323846

// ---------------- device globals (scratch + tables; no runtime allocs) ---------------
static __device__ float2 g_tw[512];     // exp(-2*pi*i*k/512)
static __device__ float2 g_post[512];   // DCT-II ortho post factors
static __device__ float  g_tmp[67108864];   // 256 MB intermediate (8*32*512*512)

// ---------------- complex helpers ----------------
__device__ __forceinline__ float2 cadd(float2 a, float2 b){ return make_float2(a.x+b.x, a.y+b.y); }
__device__ __forceinline__ float2 csub(float2 a, float2 b){ return make_float2(a.x-b.x, a.y-b.y); }
__device__ __forceinline__ float2 cmul(float2 a, float2 b){
    return make_float2(a.x*b.x - a.y*b.y, a.x*b.y + a.y*b.x);
}
__device__ __forceinline__ float2 mul_mi(float2 a){ return make_float2(a.y, -a.x); } // * (-i)

// natural-order 8-point DFT (DIF), in place
__device__ __forceinline__ void dft8(float2 v[8]){
    const float K = 0.70710678118654752440f;
    float2 t0=cadd(v[0],v[4]), t1=cadd(v[1],v[5]), t2=cadd(v[2],v[6]), t3=cadd(v[3],v[7]);
    float2 u0=csub(v[0],v[4]);
    float2 s1=csub(v[1],v[5]);
    float2 u1=make_float2(K*(s1.x+s1.y), K*(s1.y-s1.x));      // * (K,-K)
    float2 u2=mul_mi(csub(v[2],v[6]));                        // * (0,-1)
    float2 s3=csub(v[3],v[7]);
    float2 u3=make_float2(K*(s3.y-s3.x), -K*(s3.x+s3.y));     // * (-K,-K)
    float2 d0=cadd(t0,t2), d1=cadd(t1,t3), d2=csub(t0,t2), d3=mul_mi(csub(t1,t3));
    v[0]=cadd(d0,d1); v[4]=csub(d0,d1); v[2]=cadd(d2,d3); v[6]=csub(d2,d3);
    float2 e0=cadd(u0,u2), e1=cadd(u1,u3), e2=csub(u0,u2), e3=mul_mi(csub(u1,u3));
    v[1]=cadd(e0,e1); v[5]=csub(e0,e1); v[3]=cadd(e2,e3); v[7]=csub(e2,e3);
}

// padded shared index: breaks power-of-2 bank patterns; max 511 -> 574 (< 576)
__device__ __forceinline__ int padi(int i){ return i + (i >> 3); }

// Stockham radix-8 512-pt FFT. Permuted REAL input already resides at re[padi(idx)].
// 64 threads per sequence. On return: v[m] = Z[j + 64*m]. Contains __syncthreads.
__device__ __forceinline__ void fft512_shared(float* re, float* im, int j, float2 v[8]){
    // ---- stage 1 (Ns=1): read real input
    #pragma unroll
    for (int r=0;r<8;r++) v[r] = make_float2(re[padi(j + (r<<6))], 0.f);
    dft8(v);
    __syncthreads();
    #pragma unroll
    for (int r=0;r<8;r++){ int d=(j<<3)+r; re[padi(d)]=v[r].x; im[padi(d)]=v[r].y; }
    __syncthreads();
    // ---- stage 2 (Ns=8)
    #pragma unroll
    for (int r=0;r<8;r++){ int s=padi(j+(r<<6)); v[r]=make_float2(re[s], im[s]); }
    {
        int jm = j & 7;
        #pragma unroll
        for (int r=1;r<8;r++) v[r] = cmul(v[r], g_tw[(r*jm)<<3]);
    }
    dft8(v);
    __syncthreads();
    {
        int b2 = ((j>>3)<<6) + (j&7);
        #pragma unroll
        for (int r=0;r<8;r++){ int d=b2+(r<<3); re[padi(d)]=v[r].x; im[padi(d)]=v[r].y; }
    }
    __syncthreads();
    // ---- stage 3 (Ns=64): natural-order output across v[]
    #pragma unroll
    for (int r=0;r<8;r++){ int s=padi(j+(r<<6)); v[r]=make_float2(re[s], im[s]); }
    #pragma unroll
    for (int r=1;r<8;r++) v[r] = cmul(v[r], g_tw[r*j]);
    dft8(v);
}

// ---------------- table init --------------------------------------------------------
__global__ void init_tables(){
    int k = threadIdx.x;
    if (k < 512){
        double ang = -2.0 * PI_D * (double)k / 512.0;
        g_tw[k] = make_float2((float)cos(ang), (float)sin(ang));
        double th = PI_D * (double)k / 1024.0;               // pi*k/(2N), N=512
        double s2 = (k==0) ? (1.0/sqrt(512.0)) : (1.0/16.0); // 2*ortho scale
        g_post[k] = make_float2((float)(s2*cos(th)), (float)(s2*sin(th)));
    }
}

// ---------------- pass 1: DCT-II along W (contiguous rows) --------------------------
// 512 threads = 8 rows/block, 64 threads per row. grid = 16384.
__global__ void __launch_bounds__(512) dct_pass1(const float* __restrict__ x){
    __shared__ float sre[8*576];
    __shared__ float sim[8*576];
    int tid = threadIdx.x;
    size_t base = (size_t)blockIdx.x * 4096;   // 8 rows * 512

    // fully-coalesced staged load, store Makhoul-permuted
    #pragma unroll
    for (int it=0; it<8; it++){
        int e  = tid + (it<<9);                // 0..4095
        int rl = e >> 9, pos = e & 511;
        int idx = (pos & 1) ? (511 - (pos>>1)) : (pos>>1);
        sre[rl*576 + padi(idx)] = x[base + e];
    }
    __syncthreads();

    int j = tid & 63, rl = tid >> 6;
    float2 v[8];
    fft512_shared(sre + rl*576, sim + rl*576, j, v);

    float* yr = g_tmp + base + ((size_t)rl << 9);
    #pragma unroll
    for (int r=0;r<8;r++){
        int k = j + (r<<6);
        float2 p = g_post[k];
        yr[k] = v[r].x*p.x + v[r].y*p.y;       // 128B-coalesced
    }
}

// ---------------- pass 2: DCT-II along H --------------------------------------------
// 512 threads, 32-column tile (full cachelines), 4 rounds of 8 column-FFTs.
// grid = (16, 256). Dynamic smem: tile[512*33] + wre[8*576] + wim[8*576].
__global__ void __launch_bounds__(512) dct_pass2(float* __restrict__ out){
    extern __shared__ float smem[];
    float* tile = smem;                 // 512*33 = 16896
    float* wre  = smem + 16896;         // 8*576  = 4608
    float* wim  = wre + 4608;

    int tid = threadIdx.x;
    size_t ibase = (size_t)blockIdx.y * 262144 + ((size_t)blockIdx.x << 5);

    // load 512(H) x 32(W) tile, full 128B lines
    #pragma unroll
    for (int it=0; it<32; it++){
        int e = tid + (it<<9);                 // 0..16383
        int h = e >> 5, c = e & 31;
        tile[h*33 + c] = g_tmp[ibase + ((size_t)h<<9) + c];
    }
    __syncthreads();

    int j = tid & 63, csub = tid >> 6;         // 8 columns per round

    #pragma unroll 1
    for (int cc=0; cc<4; cc++){
        int col = (cc<<3) + csub;
        float* re = wre + csub*576;
        float* im = wim + csub*576;

        // Makhoul permute: tile column -> workspace (stride-33 reads, conflict-free)
        #pragma unroll
        for (int r=0;r<8;r++){
            int pos = j + (r<<6);
            int idx = (pos & 1) ? (511 - (pos>>1)) : (pos>>1);
            re[padi(idx)] = tile[pos*33 + col];
        }
        __syncthreads();

        float2 v[8];
        fft512_shared(re, im, j, v);

        // DCT post + write results back into the consumed tile columns
        #pragma unroll
        for (int r=0;r<8;r++){
            int k = j + (r<<6);
            float2 p = g_post[k];
            tile[k*33 + col] = v[r].x*p.x + v[r].y*p.y;
        }
        __syncthreads();   // protect workspace before next round's permute
    }

    // coalesced store of the whole transformed tile
    #pragma unroll
    for (int it=0; it<32; it++){
        int e = tid + (it<<9);
        int h = e >> 5, c = e & 31;
        out[ibase + ((size_t)h<<9) + c] = tile[h*33 + c];
    }
}

// ---------------- launch ------------------------------------------------------------
extern "C" void kernel_launch(void* const* d_in, const int* in_sizes, int n_in,
                              void* d_out, int out_size){
    const float* x = (const float*)d_in[0];
    float* out = (float*)d_out;

    const int smem2 = (16896 + 2*4608) * 4;   // 104448 bytes
    cudaFuncSetAttribute(dct_pass2, cudaFuncAttributeMaxDynamicSharedMemorySize, smem2);

    init_tables<<<1, 512>>>();
    dct_pass1<<<16384, 512>>>(x);
    dim3 g2(16, 256);
    dct_pass2<<<g2, 512, smem2>>>(out);
    (void)in_sizes; (void)n_in; (void)out_size;
}

// round 4
// speedup vs baseline: 1.4726x; 1.4726x over previous
#include <cuda_runtime.h>

#define PI_D 3.14159265358979323846

// ---------------- device globals (scratch + tables; no runtime allocs) ---------------
static __device__ float2 g_tw[512];       // W_512^k = exp(-2*pi*i*k/512)
static __device__ float4 g_u[256];        // untangle coeffs (a1,b1,a2,b2)
static __device__ float  g_tmp[67108864]; // 256 MB intermediate (8*32*512*512)

// ---------------- complex helpers ----------------
__device__ __forceinline__ float2 cadd(float2 a, float2 b){ return make_float2(a.x+b.x, a.y+b.y); }
__device__ __forceinline__ float2 csub(float2 a, float2 b){ return make_float2(a.x-b.x, a.y-b.y); }
__device__ __forceinline__ float2 cmul(float2 a, float2 b){
    return make_float2(a.x*b.x - a.y*b.y, a.x*b.y + a.y*b.x);
}
__device__ __forceinline__ float2 mul_mi(float2 a){ return make_float2(a.y, -a.x); } // * (-i)

// natural-order 8-point DFT, in place
__device__ __forceinline__ void dft8(float2 v[8]){
    const float K = 0.70710678118654752440f;
    float2 t0=cadd(v[0],v[4]), t1=cadd(v[1],v[5]), t2=cadd(v[2],v[6]), t3=cadd(v[3],v[7]);
    float2 u0=csub(v[0],v[4]);
    float2 s1=csub(v[1],v[5]);
    float2 u1=make_float2(K*(s1.x+s1.y), K*(s1.y-s1.x));      // * (K,-K)
    float2 u2=mul_mi(csub(v[2],v[6]));                        // * (0,-1)
    float2 s3=csub(v[3],v[7]);
    float2 u3=make_float2(K*(s3.y-s3.x), -K*(s3.x+s3.y));     // * (-K,-K)
    float2 d0=cadd(t0,t2), d1=cadd(t1,t3), d2=csub(t0,t2), d3=mul_mi(csub(t1,t3));
    v[0]=cadd(d0,d1); v[4]=csub(d0,d1); v[2]=cadd(d2,d3); v[6]=csub(d2,d3);
    float2 e0=cadd(u0,u2), e1=cadd(u1,u3), e2=csub(u0,u2), e3=mul_mi(csub(u1,u3));
    v[1]=cadd(e0,e1); v[5]=csub(e0,e1); v[3]=cadd(e2,e3); v[7]=csub(e2,e3);
}

// natural-order 4-point DFT, in place
__device__ __forceinline__ void dft4(float2 v[4]){
    float2 t0=cadd(v[0],v[2]), t1=csub(v[0],v[2]);
    float2 t2=cadd(v[1],v[3]), t3=mul_mi(csub(v[1],v[3]));
    v[0]=cadd(t0,t2); v[1]=cadd(t1,t3); v[2]=csub(t0,t2); v[3]=csub(t1,t3);
}

// padding for bank-friendly shared indexing
__device__ __forceinline__ int padi(int i){ return i + (i >> 3); }   // workspace (max 255 -> 286)

// ---- 256-pt Stockham FFT, one warp, radices 8*8*4. -----------------------------------
// Input: z[m] = packed input at position j+32m. Workspace re[288], im[288] per warp.
// Output: z[m] = Z[j + 32m] (natural order). Only __syncwarp inside.
__device__ __forceinline__ void fft256_warp(float* re, float* im, int j, float2 z[8]){
    // stage 1 (Ns=1, no twiddle)
    dft8(z);
    #pragma unroll
    for (int r=0;r<8;r++){ int d=(j<<3)+r; re[padi(d)]=z[r].x; im[padi(d)]=z[r].y; }
    __syncwarp();
    // stage 2 (Ns=8): twiddle W_64^{r*(j mod 8)}
    #pragma unroll
    for (int r=0;r<8;r++){ int s=padi(j+(r<<5)); z[r]=make_float2(re[s], im[s]); }
    {
        int jm = j & 7;
        #pragma unroll
        for (int r=1;r<8;r++) z[r] = cmul(z[r], g_tw[(r*jm)<<3]);
    }
    dft8(z);
    __syncwarp();
    {
        int b = ((j>>3)<<6) + (j&7);
        #pragma unroll
        for (int r=0;r<8;r++){ int d=b+(r<<3); re[padi(d)]=z[r].x; im[padi(d)]=z[r].y; }
    }
    __syncwarp();
    // stage 3 (Ns=64, radix 4): two butterflies per thread, twiddle W_256^{r*jj}
    #pragma unroll
    for (int g=0; g<2; g++){
        int jj = j + (g<<5);
        float2 v4[4];
        #pragma unroll
        for (int r=0;r<4;r++){ int s=padi(jj+(r<<6)); v4[r]=make_float2(re[s], im[s]); }
        #pragma unroll
        for (int r=1;r<4;r++) v4[r] = cmul(v4[r], g_tw[2*r*jj]);
        dft4(v4);
        #pragma unroll
        for (int r=0;r<4;r++) z[2*r+g] = v4[r];
    }
}

// ---- untangle: Z[k] of packed FFT -> two DCT outputs per register --------------------
// zz[m]=Z[j+32m]. o1[m]=X[k] (k=j+32m), o2[m]=X[512-k] (k>0) or X[256] (k==0).
__device__ __forceinline__ void untangle(const float2 zz[8], int j, float o1[8], float o2[8]){
    const unsigned full = 0xffffffffu;
    int src = (32 - j) & 31;
    #pragma unroll
    for (int m=0;m<8;m++){
        int k = j + (m<<5);
        float zcx = __shfl_sync(full, zz[7-m].x, src);
        float zcy = __shfl_sync(full, zz[7-m].y, src);
        if (j == 0){ zcx = zz[(8-m)&7].x; zcy = zz[(8-m)&7].y; }  // lane-0 partner is own reg
        float2 z0 = zz[m];
        float Er = 0.5f*(z0.x + zcx), Ei = 0.5f*(z0.y - zcy);
        float Or = 0.5f*(z0.y + zcy), Oi = 0.5f*(zcx - z0.x);
        float2 w = g_tw[k];
        float Vr = Er + w.x*Or - w.y*Oi;
        float Vi = Ei + w.x*Oi + w.y*Or;
        float4 u = g_u[k];
        o1[m] = u.x*Vr + u.y*Vi;
        o2[m] = u.z*Vr - u.w*Vi;
        if (k == 0) o2[m] = u.z*(z0.x - z0.y);   // X[256] = cos(pi/4)/16 * (Zr - Zi)
    }
}

// ---------------- table init --------------------------------------------------------
__global__ void init_tables(){
    int k = threadIdx.x;
    if (k < 512){
        double a = -2.0 * PI_D * (double)k / 512.0;
        g_tw[k] = make_float2((float)cos(a), (float)sin(a));
    }
    if (k < 256){
        double th = PI_D * (double)k / 1024.0;
        double s  = (k==0) ? (1.0/sqrt(512.0)) : (1.0/16.0);
        float4 u;
        u.x = (float)(s*cos(th));            // a1
        u.y = (float)(s*sin(th));            // b1
        u.z = (float)(sin(th)/16.0);         // a2  (X[512-k] = a2*Vr - b2*Vi)
        u.w = (float)(cos(th)/16.0);         // b2
        if (k == 0){ u.z = (float)(cos(PI_D/4.0)/16.0); u.w = 0.f; }
        g_u[k] = u;
    }
}

// ---------------- pass 1: DCT-II along W (one warp per row) -------------------------
// 512 threads = 16 rows/block. grid = 8192. No __syncthreads.
__global__ void __launch_bounds__(512) dct_pass1(const float4* __restrict__ x){
    __shared__ float sre[16*288];
    __shared__ float sim[16*288];
    int tid = threadIdx.x, j = tid & 31, w = tid >> 5;
    size_t row = (size_t)blockIdx.x * 16 + w;
    const float4* xr = x + row * 128;

    // 4 coalesced LDG.128 cover the whole row
    float4 f4[4];
    #pragma unroll
    for (int t=0;t<4;t++) f4[t] = xr[j + (t<<5)];

    // assemble Makhoul-packed complex input: z[m] = v[2q] + i*v[2q+1], q=j+32m
    float2 z[8];
    #pragma unroll
    for (int m=0;m<4;m++) z[m] = make_float2(f4[m].x, f4[m].z);
    const unsigned full = 0xffffffffu;
    int srcl = 31 - j;
    #pragma unroll
    for (int m=4;m<8;m++){
        float a = __shfl_sync(full, f4[7-m].w, srcl);
        float b = __shfl_sync(full, f4[7-m].y, srcl);
        z[m] = make_float2(a, b);
    }

    fft256_warp(sre + w*288, sim + w*288, j, z);

    float o1[8], o2[8];
    untangle(z, j, o1, o2);

    float* yr = g_tmp + row * 512;
    #pragma unroll
    for (int m=0;m<8;m++){
        int k = j + (m<<5);
        yr[k] = o1[m];
        int k2 = (k == 0) ? 256 : (512 - k);
        yr[k2] = o2[m];
    }
}

// ---------------- pass 2: DCT-II along H (one warp per column) ----------------------
// 512 threads = 16 columns/block; tile column doubles as FFT workspace. grid=(32,256).
__global__ void __launch_bounds__(512) dct_pass2(float* __restrict__ out){
    __shared__ float tile[16*577];         // [col][padi(h)], col stride 577 (odd mod 32)
    int tid = threadIdx.x, j = tid & 31, w = tid >> 5;
    size_t ibase = (size_t)blockIdx.y * 262144 + ((size_t)blockIdx.x << 4);

    // cooperative load: 512(H) x 16(W) tile
    #pragma unroll
    for (int it=0; it<16; it++){
        int e = tid + (it<<9);             // 0..8191
        int h = e >> 4, c = e & 15;
        tile[c*577 + padi(h)] = g_tmp[ibase + ((size_t)h<<9) + c];
    }
    __syncthreads();

    float* col = tile + w*577;

    // consume own column into registers (Makhoul-packed)
    float2 z[8];
    #pragma unroll
    for (int m=0;m<8;m++){
        int q = j + (m<<5);
        float a, b;
        if (m < 4){ a = col[padi(4*q)];      b = col[padi(4*q+2)]; }
        else      { a = col[padi(1023-4*q)]; b = col[padi(1021-4*q)]; }
        z[m] = make_float2(a, b);
    }
    __syncwarp();   // all reads done before column is reused as workspace

    fft256_warp(col, col + 288, j, z);     // workspace aliases the consumed column

    float o1[8], o2[8];
    untangle(z, j, o1, o2);
    __syncwarp();   // stage-3 shared reads done before overwriting

    #pragma unroll
    for (int m=0;m<8;m++){
        int k = j + (m<<5);
        col[padi(k)] = o1[m];
        int k2 = (k == 0) ? 256 : (512 - k);
        col[padi(k2)] = o2[m];
    }
    __syncthreads();

    // cooperative store
    #pragma unroll
    for (int it=0; it<16; it++){
        int e = tid + (it<<9);
        int h = e >> 4, c = e & 15;
        out[ibase + ((size_t)h<<9) + c] = tile[c*577 + padi(h)];
    }
}

// ---------------- launch ------------------------------------------------------------
extern "C" void kernel_launch(void* const* d_in, const int* in_sizes, int n_in,
                              void* d_out, int out_size){
    const float4* x = (const float4*)d_in[0];
    float* out = (float*)d_out;

    init_tables<<<1, 512>>>();
    dct_pass1<<<8192, 512>>>(x);           // 131072 rows, 16/block
    dim3 g2(32, 256);                      // 512/16 column-groups x 256 images
    dct_pass2<<<g2, 512>>>(out);
    (void)in_sizes; (void)n_in; (void)out_size;
}